// round 8
// baseline (speedup 1.0000x reference)
#include <cuda_runtime.h>
#include <math_constants.h>

// Problem shape (fixed): B=32, H=16, N=1024, D=128, fp32.
#define Bc 32
#define Hc 16
#define Nc 1024
#define Dc 128
#define D4 (Dc / 4)                 // 32 float4 per row
#define NROWS (Bc * Hc * Nc)        // 524288
#define NBH (Bc * Hc)               // 512
#define NT1TILES 8192               // t1sum: 2048 float4 (64 rows) per block
#define T1_PER_BH (NT1TILES / NBH)  // 16 partials per bh
#define TILES_PER_BH 32             // 32-row tiles
#define NGROUPS 4
#define TILES_PER_GROUP (NROWS / 32 / NGROUPS)   // 4096

// Scratch (device globals; allocation forbidden). Zero-initialized.
__device__ float g_score [NROWS];        // per-row score (t . w2)   2 MB
__device__ float g_part  [NT1TILES];     // per-tile t1.w1 partials  32 KB
__device__ float g_factor[NROWS];        // attn + 1                 2 MB
__device__ int   g_count [NBH];          // ticket counters (self-resetting)

// ---------------------------------------------------------------------------
// Kernel 1: t1 . w1 partial sums (whole tensor, one pass, evict-first).
// ---------------------------------------------------------------------------
__global__ __launch_bounds__(256)
void t1sum_kernel(const float* __restrict__ t1,
                  const float* __restrict__ w)
{
    __shared__ float s_red[8];
    const int tid  = threadIdx.x;
    const size_t base = (size_t)blockIdx.x * 2048;
    const float4* tv = reinterpret_cast<const float4*>(t1);
    const float4  wv = reinterpret_cast<const float4*>(w)[tid & 31];

    float acc = 0.f;
    #pragma unroll
    for (int k = 0; k < 8; k++) {
        float4 v = __ldcs(tv + base + tid + k * 256);
        acc += v.x * wv.x + v.y * wv.y + v.z * wv.z + v.w * wv.w;
    }
    #pragma unroll
    for (int o = 16; o > 0; o >>= 1)
        acc += __shfl_xor_sync(0xffffffffu, acc, o);
    if ((tid & 31) == 0) s_red[tid >> 5] = acc;
    __syncthreads();
    if (tid == 0)
        g_part[blockIdx.x] = s_red[0] + s_red[1] + s_red[2] + s_red[3]
                           + s_red[4] + s_red[5] + s_red[6] + s_red[7];
}

// ---------------------------------------------------------------------------
// Kernel 2 (per group): per-row scores for 128 bh's, t read with DEFAULT
// policy (fills L2 for the scale pass). Ticket: the last-finishing tile of
// each bh runs the (tiny) softmax and writes g_factor.
// ---------------------------------------------------------------------------
__global__ __launch_bounds__(256)
void score_softmax_kernel(const float* __restrict__ t,
                          const int*   __restrict__ padding,
                          const float* __restrict__ w,
                          const float* __restrict__ bias,
                          int tile0)
{
    __shared__ float s_score[Nc];
    __shared__ float s_red[8];
    __shared__ int   s_ticket;
    __shared__ int   s_padd;

    const int tile = tile0 + blockIdx.x;
    const int bh   = tile >> 5;
    const int tid  = threadIdx.x;
    const int wid  = tid >> 5;
    const int lane = tid & 31;
    const int g    = lane >> 3;
    const int sub  = lane & 7;

    // ---- scores: quad-per-warp (proven 84% DRAM layout) ----
    const int row = tile * 32 + wid * 4 + g;
    const float4* trow = reinterpret_cast<const float4*>(t) + (size_t)row * D4;
    const float4* wf   = reinterpret_cast<const float4*>(w);

    float4 c0 = trow[sub];
    float4 c1 = trow[sub + 8];
    float4 c2 = trow[sub + 16];
    float4 c3 = trow[sub + 24];

    float4 u0 = wf[D4 + sub],      u1 = wf[D4 + sub + 8];
    float4 u2 = wf[D4 + sub + 16], u3 = wf[D4 + sub + 24];

    float sc = c0.x*u0.x + c0.y*u0.y + c0.z*u0.z + c0.w*u0.w
             + c1.x*u1.x + c1.y*u1.y + c1.z*u1.z + c1.w*u1.w
             + c2.x*u2.x + c2.y*u2.y + c2.z*u2.z + c2.w*u2.w
             + c3.x*u3.x + c3.y*u3.y + c3.z*u3.z + c3.w*u3.w;

    sc += __shfl_xor_sync(0xffffffffu, sc, 1);
    sc += __shfl_xor_sync(0xffffffffu, sc, 2);
    sc += __shfl_xor_sync(0xffffffffu, sc, 4);
    if (sub == 0) g_score[row] = sc;

    if (tid == 0) s_padd = Nc;
    __threadfence();                 // publish g_score before the ticket
    __syncthreads();
    if (tid == 0) s_ticket = atomicAdd(&g_count[bh], 1);
    __syncthreads();
    if (s_ticket != TILES_PER_BH - 1) return;

    // ---- LAST tile of this bh: tiny softmax (~12 KB of traffic) ----
    __threadfence();                 // acquire: see all g_score writes

    {
        const int* pb = padding + (bh >> 4) * Nc;   // b = bh / Hc
        int local = Nc;
        #pragma unroll
        for (int n = tid; n < Nc; n += 256)
            if (pb[n] == 0) local = min(local, n);
        if (local < Nc) atomicMin(&s_padd, local);
    }

    if (wid == 0) {
        float v = (lane < T1_PER_BH) ? g_part[bh * T1_PER_BH + lane] : 0.f;
        #pragma unroll
        for (int o = 16; o > 0; o >>= 1)
            v += __shfl_xor_sync(0xffffffffu, v, o);
        if (lane == 0) s_red[0] = v;
    }
    __syncthreads();
    const float base = bias[0] + s_red[0];
    const int   padd = s_padd;
    __syncthreads();

    const float* sc_g = g_score + bh * Nc;
    float m = -CUDART_INF_F;
    #pragma unroll
    for (int n = tid; n < Nc; n += 256) {
        float s = sc_g[n] + base;
        s_score[n] = s;
        if (n < padd) m = fmaxf(m, s);
    }
    #pragma unroll
    for (int o = 16; o > 0; o >>= 1)
        m = fmaxf(m, __shfl_xor_sync(0xffffffffu, m, o));
    if (lane == 0) s_red[wid] = m;
    __syncthreads();
    float mx = fmaxf(fmaxf(fmaxf(s_red[0], s_red[1]), fmaxf(s_red[2], s_red[3])),
                     fmaxf(fmaxf(s_red[4], s_red[5]), fmaxf(s_red[6], s_red[7])));

    float esum = 0.f;
    #pragma unroll
    for (int n = tid; n < Nc; n += 256) {
        float e = (n < padd) ? __expf(s_score[n] - mx) : 0.f;
        s_score[n] = e;
        esum += e;
    }
    #pragma unroll
    for (int o = 16; o > 0; o >>= 1)
        esum += __shfl_xor_sync(0xffffffffu, esum, o);
    __syncthreads();
    if (lane == 0) s_red[wid] = esum;
    __syncthreads();
    float tot = s_red[0] + s_red[1] + s_red[2] + s_red[3]
              + s_red[4] + s_red[5] + s_red[6] + s_red[7];
    const float inv = (tot > 0.f) ? (1.f / tot) : 0.f;

    float* fout = g_factor + bh * Nc;
    #pragma unroll
    for (int n = tid; n < Nc; n += 256)
        fout[n] = fmaf(s_score[n], inv, 1.f);

    if (tid == 0) atomicExch(&g_count[bh], 0);   // reset for graph replay
}

// ---------------------------------------------------------------------------
// Kernel 3 (per group): out = t * factor. t[group] (64 MB) is L2-resident
// from the score pass -> reads are L2 hits. Writes evict-first.
// ---------------------------------------------------------------------------
__global__ __launch_bounds__(256)
void scale_kernel(const float* __restrict__ t, float* __restrict__ out,
                  int tile0)
{
    const size_t base = ((size_t)tile0 + blockIdx.x) * 1024;
    const int    tid  = threadIdx.x;
    const float4* tv = reinterpret_cast<const float4*>(t);
    float4* ov = reinterpret_cast<float4*>(out);

    float4 v0 = __ldcs(tv + base + tid);          // hit -> free the line
    float4 v1 = __ldcs(tv + base + tid + 256);
    float4 v2 = __ldcs(tv + base + tid + 512);
    float4 v3 = __ldcs(tv + base + tid + 768);

    const int row0 = (int)(base >> 5) + (tid >> 5);
    float f0 = g_factor[row0];
    float f1 = g_factor[row0 + 8];
    float f2 = g_factor[row0 + 16];
    float f3 = g_factor[row0 + 24];

    v0.x *= f0; v0.y *= f0; v0.z *= f0; v0.w *= f0;
    v1.x *= f1; v1.y *= f1; v1.z *= f1; v1.w *= f1;
    v2.x *= f2; v2.y *= f2; v2.z *= f2; v2.w *= f2;
    v3.x *= f3; v3.y *= f3; v3.z *= f3; v3.w *= f3;

    __stcs(ov + base + tid,       v0);
    __stcs(ov + base + tid + 256, v1);
    __stcs(ov + base + tid + 512, v2);
    __stcs(ov + base + tid + 768, v3);
}

extern "C" void kernel_launch(void* const* d_in, const int* in_sizes, int n_in,
                              void* d_out, int out_size)
{
    const float* t1      = (const float*)d_in[0];
    const float* t       = (const float*)d_in[1];
    const int*   padding = (const int*)d_in[2];

    const float* w = nullptr;
    for (int i = 3; i < n_in; i++)
        if (in_sizes[i] == 2 * Dc) { w = (const float*)d_in[i]; }
    const float* bias = (const float*)d_in[n_in - 1];

    float* out = (float*)d_out;

    t1sum_kernel<<<NT1TILES, 256>>>(t1, w);

    for (int g = 0; g < NGROUPS; g++) {
        const int tile0 = g * TILES_PER_GROUP;
        score_softmax_kernel<<<TILES_PER_GROUP, 256>>>(t, padding, w, bias, tile0);
        scale_kernel<<<TILES_PER_GROUP, 256>>>(t, out, tile0);
    }
    (void)out_size;
}

// round 9
// speedup vs baseline: 1.4543x; 1.4543x over previous
#include <cuda_runtime.h>
#include <math_constants.h>

// Problem shape (fixed): B=32, H=16, N=1024, D=128, fp32.
// KEY IDENTITY: score = base(b,h) + dot(t[n], w2) + bias, and softmax is
// shift-invariant per (b,h)  =>  attn depends ONLY on dot(t[n], w2).
// transformer_t_1, w1 and concat_b never need to be touched.
#define Bc 32
#define Hc 16
#define Nc 1024
#define Dc 128
#define D4 (Dc / 4)                 // 32 float4 per row
#define NROWS (Bc * Hc * Nc)        // 524288

// Scratch (device globals; allocation is forbidden).
__device__ float g_score [NROWS];        // per-row score (t . w2)   2 MB
__device__ float g_factor[NROWS];        // attn + 1                 2 MB

// ---------------------------------------------------------------------------
// Kernel 1: per-row scores (t . w2). Quad-per-warp layout (proven 84% DRAM).
// One quad (4 rows) per warp: g = lane>>3 row-in-quad, sub = lane&7 chunk.
// ---------------------------------------------------------------------------
__global__ __launch_bounds__(256)
void score_kernel(const float* __restrict__ t,
                  const float* __restrict__ w)      // [256]: w1 | w2
{
    const int warp = (blockIdx.x * blockDim.x + threadIdx.x) >> 5;
    const int lane = threadIdx.x & 31;
    const int g    = lane >> 3;
    const int sub  = lane & 7;
    const int row  = warp * 4 + g;

    const float4* trow = reinterpret_cast<const float4*>(t) + (size_t)row * D4;
    const float4* wf   = reinterpret_cast<const float4*>(w);

    float4 c0 = trow[sub];
    float4 c1 = trow[sub + 8];
    float4 c2 = trow[sub + 16];
    float4 c3 = trow[sub + 24];

    float4 u0 = wf[D4 + sub],      u1 = wf[D4 + sub + 8];
    float4 u2 = wf[D4 + sub + 16], u3 = wf[D4 + sub + 24];

    float sc = c0.x*u0.x + c0.y*u0.y + c0.z*u0.z + c0.w*u0.w
             + c1.x*u1.x + c1.y*u1.y + c1.z*u1.z + c1.w*u1.w
             + c2.x*u2.x + c2.y*u2.y + c2.z*u2.z + c2.w*u2.w
             + c3.x*u3.x + c3.y*u3.y + c3.z*u3.z + c3.w*u3.w;

    sc += __shfl_xor_sync(0xffffffffu, sc, 1);
    sc += __shfl_xor_sync(0xffffffffu, sc, 2);
    sc += __shfl_xor_sync(0xffffffffu, sc, 4);
    if (sub == 0) g_score[row] = sc;       // lanes 0,8,16,24
}

// ---------------------------------------------------------------------------
// Kernel 2: one block per (b,h). padd + softmax over raw scores (the constant
// base cancels in softmax), write factor = attn + 1. (~6 MB traffic.)
// ---------------------------------------------------------------------------
__global__ __launch_bounds__(256)
void softmax_kernel(const int* __restrict__ padding)
{
    __shared__ float s_score[Nc];          // 4 KB
    __shared__ float s_red[8];
    __shared__ int   s_padd;

    const int bh   = blockIdx.x;
    const int b    = bh >> 4;              // Hc = 16
    const int tid  = threadIdx.x;
    const int wid  = tid >> 5;
    const int lane = tid & 31;

    if (tid == 0) s_padd = Nc;
    __syncthreads();

    // padd = first zero in padding_t[b,:] (else N)
    {
        const int* pb = padding + b * Nc;
        int local = Nc;
        #pragma unroll
        for (int n = tid; n < Nc; n += 256)
            if (pb[n] == 0) local = min(local, n);
        if (local < Nc) atomicMin(&s_padd, local);
    }
    __syncthreads();
    const int padd = s_padd;

    // load scores + max over valid
    const float* sc_g = g_score + bh * Nc;
    float m = -CUDART_INF_F;
    #pragma unroll
    for (int n = tid; n < Nc; n += 256) {
        float sc = __ldcs(sc_g + n);
        s_score[n] = sc;
        if (n < padd) m = fmaxf(m, sc);
    }
    #pragma unroll
    for (int o = 16; o > 0; o >>= 1)
        m = fmaxf(m, __shfl_xor_sync(0xffffffffu, m, o));
    if (lane == 0) s_red[wid] = m;
    __syncthreads();
    float mx = fmaxf(fmaxf(fmaxf(s_red[0], s_red[1]), fmaxf(s_red[2], s_red[3])),
                     fmaxf(fmaxf(s_red[4], s_red[5]), fmaxf(s_red[6], s_red[7])));

    float esum = 0.f;
    #pragma unroll
    for (int n = tid; n < Nc; n += 256) {
        float e = (n < padd) ? __expf(s_score[n] - mx) : 0.f;
        s_score[n] = e;
        esum += e;
    }
    #pragma unroll
    for (int o = 16; o > 0; o >>= 1)
        esum += __shfl_xor_sync(0xffffffffu, esum, o);
    __syncthreads();
    if (lane == 0) s_red[wid] = esum;
    __syncthreads();
    float tot = s_red[0] + s_red[1] + s_red[2] + s_red[3]
              + s_red[4] + s_red[5] + s_red[6] + s_red[7];
    const float inv = (tot > 0.f) ? (1.f / tot) : 0.f;

    float* fout = g_factor + bh * Nc;
    #pragma unroll
    for (int n = tid; n < Nc; n += 256)
        fout[n] = fmaf(s_score[n], inv, 1.f);   // masked e==0 -> factor 1
}

// ---------------------------------------------------------------------------
// Kernel 3: out = t * factor[row]. Loop-free tile blocks, ILP = 4.
// ---------------------------------------------------------------------------
__global__ __launch_bounds__(256)
void scale_kernel(const float* __restrict__ t, float* __restrict__ out)
{
    const int tile = (int)gridDim.x - 1 - (int)blockIdx.x;   // reverse (free)
    const size_t base = (size_t)tile * 1024;
    const int    tid  = threadIdx.x;
    const float4* tv = reinterpret_cast<const float4*>(t);
    float4* ov = reinterpret_cast<float4*>(out);

    float4 v0 = __ldcs(tv + base + tid);
    float4 v1 = __ldcs(tv + base + tid + 256);
    float4 v2 = __ldcs(tv + base + tid + 512);
    float4 v3 = __ldcs(tv + base + tid + 768);

    const int row0 = (int)(base >> 5) + (tid >> 5);
    float f0 = g_factor[row0];
    float f1 = g_factor[row0 + 8];
    float f2 = g_factor[row0 + 16];
    float f3 = g_factor[row0 + 24];

    v0.x *= f0; v0.y *= f0; v0.z *= f0; v0.w *= f0;
    v1.x *= f1; v1.y *= f1; v1.z *= f1; v1.w *= f1;
    v2.x *= f2; v2.y *= f2; v2.z *= f2; v2.w *= f2;
    v3.x *= f3; v3.y *= f3; v3.z *= f3; v3.w *= f3;

    __stcs(ov + base + tid,       v0);
    __stcs(ov + base + tid + 256, v1);
    __stcs(ov + base + tid + 512, v2);
    __stcs(ov + base + tid + 768, v3);
}

extern "C" void kernel_launch(void* const* d_in, const int* in_sizes, int n_in,
                              void* d_out, int out_size)
{
    const float* t       = (const float*)d_in[1];
    const int*   padding = (const int*)d_in[2];

    const float* w = nullptr;
    for (int i = 3; i < n_in; i++)
        if (in_sizes[i] == 2 * Dc) { w = (const float*)d_in[i]; }

    float* out = (float*)d_out;

    score_kernel<<<NROWS / 4 / 8, 256>>>(t, w);     // 16384 blocks
    softmax_kernel<<<Bc * Hc, 256>>>(padding);
    scale_kernel<<<16384, 256>>>(t, out);
    (void)out_size;
}

// round 10
// speedup vs baseline: 1.6797x; 1.1550x over previous
#include <cuda_runtime.h>
#include <math_constants.h>

// Problem shape (fixed): B=32, H=16, N=1024, D=128, fp32.
// IDENTITY: softmax is shift-invariant per (b,h) => attn depends only on
// dot(t[n], w2). transformer_t_1 / w1 / concat_b are never read.
//
// Persistent fused kernel: 128 blocks x 512 threads, 4 bh per block.
//  pass 1: stream t[bh] (DRAM, default policy) -> scores in smem
//  softmax in smem (no global scratch at all)
//  pass 2: re-read t[bh] -> L2 HIT by construction (live set 64 MB < 126 MB L2)
#define Bc 32
#define Hc 16
#define Nc 1024
#define Dc 128
#define D4 (Dc / 4)                 // 32 float4 per row
#define NBH (Bc * Hc)               // 512
#define NBLK 128
#define BH_PER_BLK (NBH / NBLK)     // 4
#define NTH 512

__global__ __launch_bounds__(NTH, 1)
void fused_kernel(const float* __restrict__ t,
                  const int*   __restrict__ padding,
                  const float* __restrict__ w,      // [256]: w1 | w2
                  float*       __restrict__ out)
{
    __shared__ float s_score[Nc];      // scores -> exp -> factor
    __shared__ float s_red[16];
    __shared__ int   s_padd;

    const int tid  = threadIdx.x;
    const int wid  = tid >> 5;         // 0..15
    const int lane = tid & 31;
    const int g    = lane >> 3;        // row in quad
    const int sub  = lane & 7;         // dim chunk

    // w2 segments resident in registers for the whole kernel
    const float4* wf = reinterpret_cast<const float4*>(w);
    const float4 u0 = wf[D4 + sub];
    const float4 u1 = wf[D4 + sub + 8];
    const float4 u2 = wf[D4 + sub + 16];
    const float4 u3 = wf[D4 + sub + 24];

    for (int i = 0; i < BH_PER_BLK; i++) {
        const int bh = blockIdx.x * BH_PER_BLK + i;
        const float4* tb = reinterpret_cast<const float4*>(t) + (size_t)bh * Nc * D4;

        if (tid == 0) s_padd = Nc;

        // ---- pass 1: scores (quad-per-warp, proven layout). 16 iters/warp.
        #pragma unroll 2
        for (int it = 0; it < 16; it++) {
            const int row = it * 64 + wid * 4 + g;
            const float4* trow = tb + row * D4;
            float4 c0 = trow[sub];
            float4 c1 = trow[sub + 8];
            float4 c2 = trow[sub + 16];
            float4 c3 = trow[sub + 24];

            float sc = c0.x*u0.x + c0.y*u0.y + c0.z*u0.z + c0.w*u0.w
                     + c1.x*u1.x + c1.y*u1.y + c1.z*u1.z + c1.w*u1.w
                     + c2.x*u2.x + c2.y*u2.y + c2.z*u2.z + c2.w*u2.w
                     + c3.x*u3.x + c3.y*u3.y + c3.z*u3.z + c3.w*u3.w;

            sc += __shfl_xor_sync(0xffffffffu, sc, 1);
            sc += __shfl_xor_sync(0xffffffffu, sc, 2);
            sc += __shfl_xor_sync(0xffffffffu, sc, 4);
            if (sub == 0) s_score[row] = sc;
        }

        // ---- padd for this bh's batch ----
        {
            const int* pb = padding + (bh >> 4) * Nc;   // b = bh / Hc
            int local = Nc;
            #pragma unroll
            for (int n = tid; n < Nc; n += NTH)
                if (pb[n] == 0) local = min(local, n);
            if (local < Nc) atomicMin(&s_padd, local);
        }
        __syncthreads();                // s_score, s_padd complete
        const int padd = s_padd;

        // ---- softmax: max ----
        float m = -CUDART_INF_F;
        #pragma unroll
        for (int n = tid; n < Nc; n += NTH)
            if (n < padd) m = fmaxf(m, s_score[n]);
        #pragma unroll
        for (int o = 16; o > 0; o >>= 1)
            m = fmaxf(m, __shfl_xor_sync(0xffffffffu, m, o));
        if (lane == 0) s_red[wid] = m;
        __syncthreads();
        float mx = -CUDART_INF_F;
        #pragma unroll
        for (int k = 0; k < 16; k++) mx = fmaxf(mx, s_red[k]);
        __syncthreads();                // s_red about to be reused

        // ---- exp + sum ----
        float esum = 0.f;
        #pragma unroll
        for (int n = tid; n < Nc; n += NTH) {
            float e = (n < padd) ? __expf(s_score[n] - mx) : 0.f;
            s_score[n] = e;
            esum += e;
        }
        #pragma unroll
        for (int o = 16; o > 0; o >>= 1)
            esum += __shfl_xor_sync(0xffffffffu, esum, o);
        if (lane == 0) s_red[wid] = esum;
        __syncthreads();
        float tot = 0.f;
        #pragma unroll
        for (int k = 0; k < 16; k++) tot += s_red[k];
        const float inv = (tot > 0.f) ? (1.f / tot) : 0.f;

        // ---- factor in place ----
        #pragma unroll
        for (int n = tid; n < Nc; n += NTH)
            s_score[n] = fmaf(s_score[n], inv, 1.f);
        __syncthreads();

        // ---- pass 2: scale. Re-read t[bh] -> L2 hits. ILP 4, 16 iters. ----
        float4* ob = reinterpret_cast<float4*>(out) + (size_t)bh * Nc * D4;
        #pragma unroll 2
        for (int j = tid; j < Nc * D4; j += NTH * 4) {
            float4 x0 = __ldcs(tb + j);
            float4 x1 = __ldcs(tb + j + NTH);
            float4 x2 = __ldcs(tb + j + NTH * 2);
            float4 x3 = __ldcs(tb + j + NTH * 3);
            float f0 = s_score[(j)           >> 5];   // warp-uniform LDS
            float f1 = s_score[(j + NTH)     >> 5];
            float f2 = s_score[(j + NTH * 2) >> 5];
            float f3 = s_score[(j + NTH * 3) >> 5];
            x0.x *= f0; x0.y *= f0; x0.z *= f0; x0.w *= f0;
            x1.x *= f1; x1.y *= f1; x1.z *= f1; x1.w *= f1;
            x2.x *= f2; x2.y *= f2; x2.z *= f2; x2.w *= f2;
            x3.x *= f3; x3.y *= f3; x3.z *= f3; x3.w *= f3;
            __stcs(ob + j,           x0);
            __stcs(ob + j + NTH,     x1);
            __stcs(ob + j + NTH * 2, x2);
            __stcs(ob + j + NTH * 3, x3);
        }
        __syncthreads();                // protect s_score before next bh
    }
}

extern "C" void kernel_launch(void* const* d_in, const int* in_sizes, int n_in,
                              void* d_out, int out_size)
{
    const float* t       = (const float*)d_in[1];
    const int*   padding = (const int*)d_in[2];

    const float* w = nullptr;
    for (int i = 3; i < n_in; i++)
        if (in_sizes[i] == 2 * Dc) { w = (const float*)d_in[i]; }

    fused_kernel<<<NBLK, NTH>>>(t, padding, w, (float*)d_out);
    (void)out_size;
}